// round 10
// baseline (speedup 1.0000x reference)
#include <cuda_runtime.h>
#include <stdint.h>

// Quantum 2x2 gate apply on qubit axis TARGET=5 of state (2,)^24 x (4,) f32.
// Converged shape: one float4-pair per thread, fully coalesced flat grid,
// 32-bit index math, default caching. DRAM-bound at the HBM3e mixed
// read/write ceiling (82.3% DRAM, 6.52 TB/s, ~74us kernel).
// R10 probe: block=128 (finer CTA granularity; bracket the block-size axis:
// 512 hurt, 256 = optimum so far).

static constexpr uint32_t SHIFT  = 18u;            // target stride in float4 units
static constexpr uint32_t NPAIRS = 1u << 23;       // 8,388,608 pairs
static constexpr int THREADS = 128;

__global__ __launch_bounds__(THREADS)
void gate_apply_kernel(const float4* __restrict__ state,
                       const float*  __restrict__ pauli,
                       float4* __restrict__ out)
{
    uint32_t v = blockIdx.x * blockDim.x + threadIdx.x;   // grid exactly covers NPAIRS

    const float p00 = pauli[0];
    const float p01 = pauli[1];
    const float p10 = pauli[2];
    const float p11 = pauli[3];

    uint32_t low  = v & ((1u << SHIFT) - 1u);
    uint32_t idx0 = ((v >> SHIFT) << (SHIFT + 1u)) | low;  // target bit = 0
    uint32_t idx1 = idx0 + (1u << SHIFT);                  // target bit = 1

    float4 s0 = state[idx0];
    float4 s1 = state[idx1];

    float4 o0, o1;
    o0.x = p00 * s0.x + p01 * s1.x;
    o0.y = p00 * s0.y + p01 * s1.y;
    o0.z = p00 * s0.z + p01 * s1.z;
    o0.w = p00 * s0.w + p01 * s1.w;

    o1.x = p10 * s0.x + p11 * s1.x;
    o1.y = p10 * s0.y + p11 * s1.y;
    o1.z = p10 * s0.z + p11 * s1.z;
    o1.w = p10 * s0.w + p11 * s1.w;

    out[idx0] = o0;
    out[idx1] = o1;
}

extern "C" void kernel_launch(void* const* d_in, const int* in_sizes, int n_in,
                              void* d_out, int out_size)
{
    const float4* state = (const float4*)d_in[0];
    const float*  pauli = (const float*)d_in[1];
    float4* out = (float4*)d_out;

    const unsigned blocks = NPAIRS / THREADS;   // 65536, exact cover
    gate_apply_kernel<<<blocks, THREADS>>>(state, pauli, out);
}